// round 1
// baseline (speedup 1.0000x reference)
#include <cuda_runtime.h>
#include <stdint.h>

#define BB 512
#define CH 16
#define HH 28
#define WW 28
#define HW 784          // 28*28
#define PH 14
#define PW 14
#define PHW 196
#define TT 8
#define NFC 100
#define NOUT 10
#define NPOOL (CH*PHW)  // 3136
#define N1 (BB*CH*HW)   // 6422528

// ---- device scratch (no allocations allowed) ----
__device__ __align__(16) uint8_t g_t1[N1];
__device__ __align__(16) uint8_t g_t2[N1];
__device__ __align__(16) uint8_t g_tp[BB*NPOOL];
__device__ __align__(16) uint8_t g_t3[BB*NFC];
__device__ __align__(16) float   g_w1T[NPOOL*NFC];
__device__ int g_cnt1[9];
__device__ int g_cnt2[9];
__device__ int g_cnt3[9];
__device__ int g_cnt4[9];

__global__ void k_zero() {
    int i = threadIdx.x;
    if (i < 9) { g_cnt1[i] = 0; g_cnt2[i] = 0; g_cnt3[i] = 0; g_cnt4[i] = 0; }
}

// w1 [100][3136] -> w1T [3136][100] for coalesced FC1 access
__global__ void k_transpose_w1(const float* __restrict__ w1) {
    int idx = blockIdx.x * 256 + threadIdx.x;
    if (idx < NFC * NPOOL) {
        int j = idx / NPOOL;
        int n = idx - j * NPOOL;
        g_w1T[n * NFC + j] = w1[idx];
    }
}

// Kernel 1: static conv (1->16 ch, 3x3 SAME) + OneSpikeIF firing time t1
__global__ void __launch_bounds__(256) k1_sconv(const float* __restrict__ x,
                                                const float* __restrict__ ws) {
    int b = blockIdx.x;
    __shared__ float sx[HW];
    __shared__ float sw[CH * 9];
    __shared__ int sh[9];
    int tid = threadIdx.x;
    for (int i = tid; i < HW; i += 256) sx[i] = x[b * HW + i];
    for (int i = tid; i < CH * 9; i += 256) sw[i] = ws[i];
    if (tid < 9) sh[tid] = 0;
    __syncthreads();
    for (int o = 0; o < CH; o++) {
        const float* w = sw + o * 9;
        for (int p = tid; p < HW; p += 256) {
            int y = p / WW, xx = p - y * WW;
            float acc = 0.f;
#pragma unroll
            for (int ky = 0; ky < 3; ky++) {
                int yy = y + ky - 1;
                if (yy < 0 || yy >= HH) continue;
#pragma unroll
                for (int kx = 0; kx < 3; kx++) {
                    int xc = xx + kx - 1;
                    if (xc < 0 || xc >= WW) continue;
                    acc += sx[yy * WW + xc] * w[ky * 3 + kx];
                }
            }
            // iterative IF sim (matches reference fp32 repeated-add rounding)
            float v = 0.f; int t1 = 8;
#pragma unroll
            for (int t = 0; t < TT; t++) { v += acc; if (v >= 1.f) { t1 = t; break; } }
            g_t1[(b * CH + o) * HW + p] = (uint8_t)t1;
            atomicAdd(&sh[t1], 1);
        }
    }
    __syncthreads();
    if (tid < 9 && sh[tid]) atomicAdd(&g_cnt1[tid], sh[tid]);
}

// Kernel 2: conv2 (16->16, 3x3 SAME) over ALL 8 timesteps at once via
// cumulative predicated accumulation; IF first-crossing -> t2.
__global__ void __launch_bounds__(256) k2_conv(const float* __restrict__ wc) {
    int b = blockIdx.x;
    __shared__ uint8_t st[CH * HW];     // 12544 B: t1 map for this batch
    __shared__ float sw[CH * CH * 9];   // 9216 B: conv weights
    __shared__ int sh[9];
    int tid = threadIdx.x;
    {
        const uint4* src = (const uint4*)(g_t1 + b * CH * HW);
        uint4* dst = (uint4*)st;
        for (int i = tid; i < CH * HW / 16; i += 256) dst[i] = src[i];
    }
    for (int i = tid; i < CH * CH * 9; i += 256) sw[i] = wc[i];
    if (tid < 9) sh[tid] = 0;
    __syncthreads();

    for (int o = 0; o < CH; o++) {
        for (int p = tid; p < HW; p += 256) {
            int y = p / WW, xx = p - y * WW;
            float A0 = 0.f, A1 = 0.f, A2 = 0.f, A3 = 0.f;
            float A4 = 0.f, A5 = 0.f, A6 = 0.f, A7 = 0.f;
            for (int i = 0; i < CH; i++) {
                const uint8_t* ti = st + i * HW;
                const float* wi = sw + (o * CH + i) * 9;
#pragma unroll
                for (int ky = 0; ky < 3; ky++) {
                    int yy = y + ky - 1;
                    if (yy < 0 || yy >= HH) continue;
#pragma unroll
                    for (int kx = 0; kx < 3; kx++) {
                        int xc = xx + kx - 1;
                        if (xc < 0 || xc >= WW) continue;
                        int tv = ti[yy * WW + xc];
                        float w = wi[ky * 3 + kx];
                        if (tv <= 0) A0 += w;
                        if (tv <= 1) A1 += w;
                        if (tv <= 2) A2 += w;
                        if (tv <= 3) A3 += w;
                        if (tv <= 4) A4 += w;
                        if (tv <= 5) A5 += w;
                        if (tv <= 6) A6 += w;
                        if (tv <= 7) A7 += w;
                    }
                }
            }
            int t2 = 8;
            if      (A0 >= 1.f) t2 = 0;
            else if (A1 >= 1.f) t2 = 1;
            else if (A2 >= 1.f) t2 = 2;
            else if (A3 >= 1.f) t2 = 3;
            else if (A4 >= 1.f) t2 = 4;
            else if (A5 >= 1.f) t2 = 5;
            else if (A6 >= 1.f) t2 = 6;
            else if (A7 >= 1.f) t2 = 7;
            g_t2[(b * CH + o) * HW + p] = (uint8_t)t2;
            atomicAdd(&sh[t2], 1);
        }
    }
    __syncthreads();
    if (tid < 9 && sh[tid]) atomicAdd(&g_cnt2[tid], sh[tid]);
}

// Kernel 3: FirstSpikePool2d == min firing time over each 2x2 window
__global__ void k3_pool() {
    int idx = blockIdx.x * 256 + threadIdx.x;
    if (idx >= BB * CH * PHW) return;
    int X = idx % PW;
    int tmp = idx / PW;
    int Y = tmp % PH;
    int bc = tmp / PH;
    const uint8_t* base = g_t2 + bc * HW + (Y * 2) * WW + X * 2;
    int m = min(min((int)base[0], (int)base[1]), min((int)base[WW], (int)base[WW + 1]));
    g_tp[idx] = (uint8_t)m;
}

// Kernel 4: FC1 cumulative crossing -> t3. tp[n] is warp-uniform, so use a
// uniform fall-through switch: only (8 - tp) FADDs per contribution.
__global__ void __launch_bounds__(128) k4_fc1() {
    int b = blockIdx.x;
    __shared__ uint8_t stp[NPOOL];
    __shared__ int sh[9];
    int tid = threadIdx.x;
    {
        const uint4* src = (const uint4*)(g_tp + b * NPOOL);
        for (int i = tid; i < NPOOL / 16; i += 128) ((uint4*)stp)[i] = src[i];
    }
    if (tid < 9) sh[tid] = 0;
    __syncthreads();
    if (tid < NFC) {
        float C[8] = {0.f, 0.f, 0.f, 0.f, 0.f, 0.f, 0.f, 0.f};
        for (int n = 0; n < NPOOL; n++) {
            int tv = stp[n];              // uniform across warp
            if (tv < 8) {
                float w = g_w1T[n * NFC + tid];
                switch (tv) {             // intentional fall-through: adds to C[tv..7]
                    case 0: C[0] += w; // fallthrough
                    case 1: C[1] += w; // fallthrough
                    case 2: C[2] += w; // fallthrough
                    case 3: C[3] += w; // fallthrough
                    case 4: C[4] += w; // fallthrough
                    case 5: C[5] += w; // fallthrough
                    case 6: C[6] += w; // fallthrough
                    case 7: C[7] += w;
                }
            }
        }
        int t3 = 8;
#pragma unroll
        for (int t = TT - 1; t >= 0; t--) if (C[t] >= 1.f) t3 = t;
        g_t3[b * NFC + tid] = (uint8_t)t3;
        atomicAdd(&sh[t3], 1);
    }
    __syncthreads();
    if (tid < 9 && sh[tid]) atomicAdd(&g_cnt3[tid], sh[tid]);
}

// Kernel 5: FC2 per-timestep inputs + exact readout IF sim + latency score
__global__ void k5_out(const float* __restrict__ w2, float* __restrict__ out) {
    int b = blockIdx.x;
    __shared__ uint8_t s3[NFC];
    int tid = threadIdx.x;  // 32 threads
    for (int i = tid; i < NFC; i += 32) s3[i] = g_t3[b * NFC + i];
    __syncthreads();
    if (tid < NOUT) {
        float O[8] = {0.f, 0.f, 0.f, 0.f, 0.f, 0.f, 0.f, 0.f};
        for (int j = 0; j < NFC; j++) {
            int tv = s3[j];               // uniform across warp
            if (tv < 8) {
                float w = w2[tid * NFC + j];
                switch (tv) {
                    case 0: O[0] += w; break;
                    case 1: O[1] += w; break;
                    case 2: O[2] += w; break;
                    case 3: O[3] += w; break;
                    case 4: O[4] += w; break;
                    case 5: O[5] += w; break;
                    case 6: O[6] += w; break;
                    case 7: O[7] += w; break;
                }
            }
        }
        float v = 0.f; int first = 8;
#pragma unroll
        for (int t = 0; t < TT; t++) {
            v += O[t];
            if (v >= 1.f) {
                v = 0.f;
                if (first == 8) first = t;
                atomicAdd(&g_cnt4[t], 1);
            }
        }
        out[b * NOUT + tid] = (first < 8) ? (float)(TT - first) / (float)TT : 0.f;
    }
}

// Kernel 6: reg_loss = sum of per-layer max firing rates over t
__global__ void k6_final(float* __restrict__ out, int write_reg) {
    if (threadIdx.x == 0 && write_reg) {
        float m1 = 0.f, m2 = 0.f, m3 = 0.f, m4 = 0.f;
        for (int t = 0; t < TT; t++) {
            m1 = fmaxf(m1, (float)g_cnt1[t] / (float)N1);
            m2 = fmaxf(m2, (float)g_cnt2[t] / (float)N1);
            m3 = fmaxf(m3, (float)g_cnt3[t] / (float)(BB * NFC));
            m4 = fmaxf(m4, (float)g_cnt4[t] / (float)(BB * NOUT));
        }
        out[BB * NOUT] = m1 + m2 + m3 + m4;
    }
}

extern "C" void kernel_launch(void* const* d_in, const int* in_sizes, int n_in,
                              void* d_out, int out_size) {
    const float* x  = (const float*)d_in[0];
    const float* ws = (const float*)d_in[1];
    const float* wc = (const float*)d_in[2];
    const float* w1 = (const float*)d_in[3];
    const float* w2 = (const float*)d_in[4];
    float* out = (float*)d_out;

    k_zero<<<1, 32>>>();
    k_transpose_w1<<<(NFC * NPOOL + 255) / 256, 256>>>(w1);
    k1_sconv<<<BB, 256>>>(x, ws);
    k2_conv<<<BB, 256>>>(wc);
    k3_pool<<<(BB * CH * PHW + 255) / 256, 256>>>();
    k4_fc1<<<BB, 128>>>();
    k5_out<<<BB, 32>>>(w2, out);
    k6_final<<<1, 1>>>(out, (out_size > BB * NOUT) ? 1 : 0);
}

// round 2
// speedup vs baseline: 1.1150x; 1.1150x over previous
#include <cuda_runtime.h>
#include <stdint.h>

#define BB 512
#define CH 16
#define HH 28
#define WW 28
#define HW 784          // 28*28
#define PH 14
#define PW 14
#define PHW 196
#define TT 8
#define NFC 100
#define NOUT 10
#define NPOOL (CH*PHW)  // 3136
#define N1 (BB*CH*HW)   // 6422528

typedef unsigned long long ull;

// ---- device scratch (no allocations allowed) ----
__device__ __align__(16) uint8_t g_t1[N1];
__device__ __align__(16) uint8_t g_t2[N1];
__device__ __align__(16) uint8_t g_tp[BB*NPOOL];
__device__ __align__(16) uint8_t g_t3[BB*NFC];
__device__ __align__(16) float   g_w1T[NPOOL*NFC];
__device__ int g_cnt1[9];
__device__ int g_cnt2[9];
__device__ int g_cnt3[9];
__device__ int g_cnt4[9];

__global__ void k_zero() {
    int i = threadIdx.x;
    if (i < 9) { g_cnt1[i] = 0; g_cnt2[i] = 0; g_cnt3[i] = 0; g_cnt4[i] = 0; }
}

// w1 [100][3136] -> w1T [3136][100]
__global__ void k_transpose_w1(const float* __restrict__ w1) {
    int idx = blockIdx.x * 256 + threadIdx.x;
    if (idx < NFC * NPOOL) {
        int j = idx / NPOOL;
        int n = idx - j * NPOOL;
        g_w1T[n * NFC + j] = w1[idx];
    }
}

// Kernel 1: static conv (1->16 ch, 3x3 SAME) + OneSpikeIF firing time t1
__global__ void __launch_bounds__(256) k1_sconv(const float* __restrict__ x,
                                                const float* __restrict__ ws) {
    int b = blockIdx.x;
    __shared__ float sx[HW];
    __shared__ float sw[CH * 9];
    __shared__ int sh[9];
    int tid = threadIdx.x;
    for (int i = tid; i < HW; i += 256) sx[i] = x[b * HW + i];
    for (int i = tid; i < CH * 9; i += 256) sw[i] = ws[i];
    if (tid < 9) sh[tid] = 0;
    __syncthreads();
    for (int o = 0; o < CH; o++) {
        const float* w = sw + o * 9;
        for (int p = tid; p < HW; p += 256) {
            int y = p / WW, xx = p - y * WW;
            float acc = 0.f;
#pragma unroll
            for (int ky = 0; ky < 3; ky++) {
                int yy = y + ky - 1;
                if (yy < 0 || yy >= HH) continue;
#pragma unroll
                for (int kx = 0; kx < 3; kx++) {
                    int xc = xx + kx - 1;
                    if (xc < 0 || xc >= WW) continue;
                    acc += sx[yy * WW + xc] * w[ky * 3 + kx];
                }
            }
            float v = 0.f; int t1 = 8;
#pragma unroll
            for (int t = 0; t < TT; t++) { v += acc; if (v >= 1.f) { t1 = t; break; } }
            g_t1[(b * CH + o) * HW + p] = (uint8_t)t1;
            atomicAdd(&sh[t1], 1);
        }
    }
    __syncthreads();
    if (tid < 9 && sh[tid]) atomicAdd(&g_cnt1[tid], sh[tid]);
}

// One t-slice of a tap: setp once, 4 predicated packed-f32x2 FMAs (8 oc).
#define TAP8(TLIT, A0, A1, A2, A3, W0, W1, W2, W3, TV, ONE)            \
    asm("{.reg .pred p; setp.le.s32 p, %9, " TLIT ";\n\t"              \
        "@p fma.rn.f32x2 %0, %4, %8, %0;\n\t"                          \
        "@p fma.rn.f32x2 %1, %5, %8, %1;\n\t"                          \
        "@p fma.rn.f32x2 %2, %6, %8, %2;\n\t"                          \
        "@p fma.rn.f32x2 %3, %7, %8, %3;}\n\t"                         \
        : "+l"(A0), "+l"(A1), "+l"(A2), "+l"(A3)                       \
        : "l"(W0), "l"(W1), "l"(W2), "l"(W3), "l"(ONE), "r"(TV))

// Kernel 2: conv2 over all 8 timesteps at once. Thread = pixel; oc-pairs
// packed into f32x2; predicates shared across all oc. Two oc-half passes.
__global__ void __launch_bounds__(392) k2_conv(const float* __restrict__ wc) {
    int b = blockIdx.x;
    int p = blockIdx.y * 392 + threadIdx.x;
    __shared__ uint8_t st[CH * 900];      // padded 30x30 maps, border = 8
    __shared__ ull sw2[CH * 9 * 8];       // [i][tap][pair] packed {w[2p],w[2p+1]}
    __shared__ int sh[9];
    int tid = threadIdx.x;

    // fill padded maps with 8, then copy interior
    for (int i = tid; i < CH * 900 / 4; i += 392)
        ((uint32_t*)st)[i] = 0x08080808u;
    if (tid < 9) sh[tid] = 0;
    __syncthreads();
    for (int idx = tid; idx < CH * HW; idx += 392) {
        int i = idx / HW, pp = idx - i * HW;
        int y = pp / WW, x = pp - y * WW;
        st[i * 900 + (y + 1) * 30 + (x + 1)] = g_t1[b * CH * HW + idx];
    }
    // pack weights: pair pr covers oc {2pr, 2pr+1}
    for (int idx = tid; idx < CH * 9 * 8; idx += 392) {
        int pr = idx & 7;
        int ik = idx >> 3;            // i*9 + k
        uint32_t lo = __float_as_uint(wc[(2 * pr) * (CH * 9) + ik]);
        uint32_t hi = __float_as_uint(wc[(2 * pr + 1) * (CH * 9) + ik]);
        sw2[idx] = ((ull)hi << 32) | lo;
    }
    __syncthreads();

    int y = p / WW, x = p - y * WW;
    const int q = (y + 1) * 30 + (x + 1);
    const ull ONE = 0x3f8000003f800000ull;

    for (int half = 0; half < 2; half++) {
        ull a[4][8];
#pragma unroll
        for (int pr = 0; pr < 4; pr++)
#pragma unroll
            for (int t = 0; t < 8; t++) a[pr][t] = 0ull;

#pragma unroll 1
        for (int i = 0; i < CH; i++) {
            const uint8_t* tp = st + i * 900 + q;
            const ull* wr = sw2 + i * 72 + half * 4;
#pragma unroll
            for (int k = 0; k < 9; k++) {
                const int dy = k / 3 - 1, dx = k % 3 - 1;
                int tv = tp[dy * 30 + dx];
                ull w0 = wr[k * 8 + 0], w1 = wr[k * 8 + 1];
                ull w2 = wr[k * 8 + 2], w3 = wr[k * 8 + 3];
                TAP8("0", a[0][0], a[1][0], a[2][0], a[3][0], w0, w1, w2, w3, tv, ONE);
                TAP8("1", a[0][1], a[1][1], a[2][1], a[3][1], w0, w1, w2, w3, tv, ONE);
                TAP8("2", a[0][2], a[1][2], a[2][2], a[3][2], w0, w1, w2, w3, tv, ONE);
                TAP8("3", a[0][3], a[1][3], a[2][3], a[3][3], w0, w1, w2, w3, tv, ONE);
                TAP8("4", a[0][4], a[1][4], a[2][4], a[3][4], w0, w1, w2, w3, tv, ONE);
                TAP8("5", a[0][5], a[1][5], a[2][5], a[3][5], w0, w1, w2, w3, tv, ONE);
                TAP8("6", a[0][6], a[1][6], a[2][6], a[3][6], w0, w1, w2, w3, tv, ONE);
                TAP8("7", a[0][7], a[1][7], a[2][7], a[3][7], w0, w1, w2, w3, tv, ONE);
            }
        }
        // extract firing times for the 8 oc of this half
#pragma unroll
        for (int pr = 0; pr < 4; pr++) {
#pragma unroll
            for (int lane = 0; lane < 2; lane++) {
                int o = half * 8 + pr * 2 + lane;
                float A[8];
#pragma unroll
                for (int t = 0; t < 8; t++) {
                    ull v = a[pr][t];
                    A[t] = __uint_as_float(lane ? (uint32_t)(v >> 32) : (uint32_t)v);
                }
                int t2 = 8;
#pragma unroll
                for (int t = TT - 1; t >= 0; t--) if (A[t] >= 1.f) t2 = t;
                g_t2[(b * CH + o) * HW + p] = (uint8_t)t2;
                atomicAdd(&sh[t2], 1);
            }
        }
    }
    __syncthreads();
    if (tid < 9 && sh[tid]) atomicAdd(&g_cnt2[tid], sh[tid]);
}

// Kernel 3: FirstSpikePool2d == min firing time over each 2x2 window
__global__ void k3_pool() {
    int idx = blockIdx.x * 256 + threadIdx.x;
    if (idx >= BB * CH * PHW) return;
    int X = idx % PW;
    int tmp = idx / PW;
    int Y = tmp % PH;
    int bc = tmp / PH;
    const uint8_t* base = g_t2 + bc * HW + (Y * 2) * WW + X * 2;
    int m = min(min((int)base[0], (int)base[1]), min((int)base[WW], (int)base[WW + 1]));
    g_tp[idx] = (uint8_t)m;
}

// Kernel 4: FC1 crossing -> t3. 4 batches/block; w1T chunk-staged in shared.
__global__ void __launch_bounds__(512) k4_fc1() {
    int b0 = blockIdx.x * 4;
    int tid = threadIdx.x;
    int bl = tid >> 7, j = tid & 127;
    __shared__ uint8_t stp[4 * NPOOL];
    __shared__ float sw1[32 * NFC];
    __shared__ int sh[9];
    {
        const uint4* src = (const uint4*)(g_tp + b0 * NPOOL);
        for (int i = tid; i < 4 * NPOOL / 16; i += 512) ((uint4*)stp)[i] = src[i];
    }
    if (tid < 9) sh[tid] = 0;
    float C[8] = {0.f, 0.f, 0.f, 0.f, 0.f, 0.f, 0.f, 0.f};
    for (int c = 0; c < NPOOL / 32; c++) {
        __syncthreads();
        for (int idx = tid; idx < 32 * NFC; idx += 512)
            sw1[idx] = g_w1T[c * 32 * NFC + idx];
        __syncthreads();
        if (j < NFC) {
            const uint8_t* tb = stp + bl * NPOOL + c * 32;
#pragma unroll 4
            for (int nl = 0; nl < 32; nl++) {
                int tv = tb[nl];                 // uniform across warp
                if (tv < 8) {
                    float w = sw1[nl * NFC + j];
                    switch (tv) {                 // intentional fall-through
                        case 0: C[0] += w; // fallthrough
                        case 1: C[1] += w; // fallthrough
                        case 2: C[2] += w; // fallthrough
                        case 3: C[3] += w; // fallthrough
                        case 4: C[4] += w; // fallthrough
                        case 5: C[5] += w; // fallthrough
                        case 6: C[6] += w; // fallthrough
                        case 7: C[7] += w;
                    }
                }
            }
        }
    }
    if (j < NFC) {
        int t3 = 8;
#pragma unroll
        for (int t = TT - 1; t >= 0; t--) if (C[t] >= 1.f) t3 = t;
        g_t3[(b0 + bl) * NFC + j] = (uint8_t)t3;
        atomicAdd(&sh[t3], 1);
    }
    __syncthreads();
    if (tid < 9 && sh[tid]) atomicAdd(&g_cnt3[tid], sh[tid]);
}

// Kernel 5: FC2 + exact readout IF sim + latency score
__global__ void k5_out(const float* __restrict__ w2, float* __restrict__ out) {
    int b = blockIdx.x;
    __shared__ uint8_t s3[NFC];
    int tid = threadIdx.x;  // 32 threads
    for (int i = tid; i < NFC; i += 32) s3[i] = g_t3[b * NFC + i];
    __syncthreads();
    if (tid < NOUT) {
        float O[8] = {0.f, 0.f, 0.f, 0.f, 0.f, 0.f, 0.f, 0.f};
        for (int jj = 0; jj < NFC; jj++) {
            int tv = s3[jj];
            if (tv < 8) {
                float w = w2[tid * NFC + jj];
                switch (tv) {
                    case 0: O[0] += w; break;
                    case 1: O[1] += w; break;
                    case 2: O[2] += w; break;
                    case 3: O[3] += w; break;
                    case 4: O[4] += w; break;
                    case 5: O[5] += w; break;
                    case 6: O[6] += w; break;
                    case 7: O[7] += w; break;
                }
            }
        }
        float v = 0.f; int first = 8;
#pragma unroll
        for (int t = 0; t < TT; t++) {
            v += O[t];
            if (v >= 1.f) {
                v = 0.f;
                if (first == 8) first = t;
                atomicAdd(&g_cnt4[t], 1);
            }
        }
        out[b * NOUT + tid] = (first < 8) ? (float)(TT - first) / (float)TT : 0.f;
    }
}

// Kernel 6: reg_loss
__global__ void k6_final(float* __restrict__ out, int write_reg) {
    if (threadIdx.x == 0 && write_reg) {
        float m1 = 0.f, m2 = 0.f, m3 = 0.f, m4 = 0.f;
        for (int t = 0; t < TT; t++) {
            m1 = fmaxf(m1, (float)g_cnt1[t] / (float)N1);
            m2 = fmaxf(m2, (float)g_cnt2[t] / (float)N1);
            m3 = fmaxf(m3, (float)g_cnt3[t] / (float)(BB * NFC));
            m4 = fmaxf(m4, (float)g_cnt4[t] / (float)(BB * NOUT));
        }
        out[BB * NOUT] = m1 + m2 + m3 + m4;
    }
}

extern "C" void kernel_launch(void* const* d_in, const int* in_sizes, int n_in,
                              void* d_out, int out_size) {
    const float* x  = (const float*)d_in[0];
    const float* ws = (const float*)d_in[1];
    const float* wc = (const float*)d_in[2];
    const float* w1 = (const float*)d_in[3];
    const float* w2 = (const float*)d_in[4];
    float* out = (float*)d_out;

    k_zero<<<1, 32>>>();
    k_transpose_w1<<<(NFC * NPOOL + 255) / 256, 256>>>(w1);
    k1_sconv<<<BB, 256>>>(x, ws);
    {
        dim3 g(BB, 2);
        k2_conv<<<g, 392>>>(wc);
    }
    k3_pool<<<(BB * CH * PHW + 255) / 256, 256>>>();
    k4_fc1<<<BB / 4, 512>>>();
    k5_out<<<BB, 32>>>(w2, out);
    k6_final<<<1, 1>>>(out, (out_size > BB * NOUT) ? 1 : 0);
}

// round 3
// speedup vs baseline: 1.4077x; 1.2625x over previous
#include <cuda_runtime.h>
#include <stdint.h>

#define BB 512
#define CH 16
#define HH 28
#define WW 28
#define HW 784
#define PH 14
#define PW 14
#define PHW 196
#define TT 8
#define NFC 100
#define NOUT 10
#define NPOOL (CH*PHW)  // 3136
#define N1 (BB*CH*HW)

typedef unsigned long long ull;

__device__ __align__(16) uint8_t g_t1[N1];
__device__ __align__(16) uint8_t g_tp[BB*NPOOL];
__device__ __align__(16) float   g_w1T[NPOOL*NFC];
__device__ int g_cnt1[9];
__device__ int g_cnt2[9];
__device__ int g_cnt3[9];
__device__ int g_cnt4[9];

__global__ void k_zero() {
    int i = threadIdx.x;
    if (i < 9) { g_cnt1[i] = 0; g_cnt2[i] = 0; g_cnt3[i] = 0; g_cnt4[i] = 0; }
}

__global__ void k_transpose_w1(const float* __restrict__ w1) {
    int idx = blockIdx.x * 256 + threadIdx.x;
    if (idx < NFC * NPOOL) {
        int j = idx / NPOOL;
        int n = idx - j * NPOOL;
        g_w1T[n * NFC + j] = w1[idx];
    }
}

// packed 16-bit x4 histogram helpers (buckets 0..7 only; bucket 8 dropped)
__device__ __forceinline__ void hist_add(ull& h0, ull& h1, int t) {
    if (t < 8) {
        if (t < 4) h0 += 1ull << (16 * t);
        else       h1 += 1ull << (16 * (t - 4));
    }
}
__device__ __forceinline__ void hist_flush_warp(ull h0, ull h1, int tid, int* sh) {
    if (tid < (blockDim.x & ~31)) {   // full warps: shfl tree
#pragma unroll
        for (int off = 16; off; off >>= 1) {
            h0 += __shfl_down_sync(0xffffffffu, h0, off);
            h1 += __shfl_down_sync(0xffffffffu, h1, off);
        }
        if ((tid & 31) == 0) {
#pragma unroll
            for (int t = 0; t < 4; t++) {
                int c0 = (int)((h0 >> (16 * t)) & 0xffff);
                int c1 = (int)((h1 >> (16 * t)) & 0xffff);
                if (c0) atomicAdd(&sh[t], c0);
                if (c1) atomicAdd(&sh[t + 4], c1);
            }
        }
    } else {                           // partial tail warp: direct
#pragma unroll
        for (int t = 0; t < 4; t++) {
            int c0 = (int)((h0 >> (16 * t)) & 0xffff);
            int c1 = (int)((h1 >> (16 * t)) & 0xffff);
            if (c0) atomicAdd(&sh[t], c0);
            if (c1) atomicAdd(&sh[t + 4], c1);
        }
    }
}

// Kernel 1: static conv + OneSpikeIF firing time t1
__global__ void __launch_bounds__(256) k1_sconv(const float* __restrict__ x,
                                                const float* __restrict__ ws) {
    int b = blockIdx.x;
    __shared__ float sx[HW];
    __shared__ float sw[CH * 9];
    __shared__ int sh[8];
    int tid = threadIdx.x;
    for (int i = tid; i < HW; i += 256) sx[i] = x[b * HW + i];
    for (int i = tid; i < CH * 9; i += 256) sw[i] = ws[i];
    if (tid < 8) sh[tid] = 0;
    __syncthreads();
    ull h0 = 0, h1 = 0;
    for (int o = 0; o < CH; o++) {
        const float* w = sw + o * 9;
        for (int p = tid; p < HW; p += 256) {
            int y = p / WW, xx = p - y * WW;
            float acc = 0.f;
#pragma unroll
            for (int ky = 0; ky < 3; ky++) {
                int yy = y + ky - 1;
                if (yy < 0 || yy >= HH) continue;
#pragma unroll
                for (int kx = 0; kx < 3; kx++) {
                    int xc = xx + kx - 1;
                    if (xc < 0 || xc >= WW) continue;
                    acc += sx[yy * WW + xc] * w[ky * 3 + kx];
                }
            }
            float v = 0.f; int t1 = 8;
#pragma unroll
            for (int t = 0; t < TT; t++) { v += acc; if (v >= 1.f) { t1 = t; break; } }
            g_t1[(b * CH + o) * HW + p] = (uint8_t)t1;
            hist_add(h0, h1, t1);
        }
    }
    hist_flush_warp(h0, h1, tid, sh);
    __syncthreads();
    if (tid < 8 && sh[tid]) atomicAdd(&g_cnt1[tid], sh[tid]);
}

#define TAP8(TLIT, A0, A1, A2, A3, W0, W1, W2, W3, TV, ONE)            \
    asm("{.reg .pred p; setp.le.s32 p, %9, " TLIT ";\n\t"              \
        "@p fma.rn.f32x2 %0, %4, %8, %0;\n\t"                          \
        "@p fma.rn.f32x2 %1, %5, %8, %1;\n\t"                          \
        "@p fma.rn.f32x2 %2, %6, %8, %2;\n\t"                          \
        "@p fma.rn.f32x2 %3, %7, %8, %3;}\n\t"                         \
        : "+l"(A0), "+l"(A1), "+l"(A2), "+l"(A3)                       \
        : "l"(W0), "l"(W1), "l"(W2), "l"(W3), "l"(ONE), "r"(TV))

#define TAP8U(A0, A1, A2, A3, W0, W1, W2, W3, ONE)                     \
    asm("fma.rn.f32x2 %0, %4, %8, %0;\n\t"                             \
        "fma.rn.f32x2 %1, %5, %8, %1;\n\t"                             \
        "fma.rn.f32x2 %2, %6, %8, %2;\n\t"                             \
        "fma.rn.f32x2 %3, %7, %8, %3;"                                 \
        : "+l"(A0), "+l"(A1), "+l"(A2), "+l"(A3)                       \
        : "l"(W0), "l"(W1), "l"(W2), "l"(W3), "l"(ONE))

// process one tap (skippable): t=0..6 predicated, t=7 unconditional
#define DO_TAP(TV, WP, A)                                                   \
    if ((TV) < 8) {                                                         \
        const ulonglong2* _w = (const ulonglong2*)(WP);                     \
        ulonglong2 _wa = _w[0], _wb = _w[1];                                \
        TAP8("0", A[0][0], A[1][0], A[2][0], A[3][0], _wa.x, _wa.y, _wb.x, _wb.y, TV, ONE); \
        TAP8("1", A[0][1], A[1][1], A[2][1], A[3][1], _wa.x, _wa.y, _wb.x, _wb.y, TV, ONE); \
        TAP8("2", A[0][2], A[1][2], A[2][2], A[3][2], _wa.x, _wa.y, _wb.x, _wb.y, TV, ONE); \
        TAP8("3", A[0][3], A[1][3], A[2][3], A[3][3], _wa.x, _wa.y, _wb.x, _wb.y, TV, ONE); \
        TAP8("4", A[0][4], A[1][4], A[2][4], A[3][4], _wa.x, _wa.y, _wb.x, _wb.y, TV, ONE); \
        TAP8("5", A[0][5], A[1][5], A[2][5], A[3][5], _wa.x, _wa.y, _wb.x, _wb.y, TV, ONE); \
        TAP8("6", A[0][6], A[1][6], A[2][6], A[3][6], _wa.x, _wa.y, _wb.x, _wb.y, TV, ONE); \
        TAP8U(     A[0][7], A[1][7], A[2][7], A[3][7], _wa.x, _wa.y, _wb.x, _wb.y, ONE);    \
    }

// Kernel 2: conv2 over all 8 timesteps, fused pool. Thread = pixel.
__global__ void __launch_bounds__(392, 2) k2_conv(const float* __restrict__ wc) {
    int b = blockIdx.x;
    int tid = threadIdx.x;
    int p = blockIdx.y * 392 + tid;
    __shared__ uint8_t st[CH * 900];              // padded 30x30 t1 maps
    __shared__ __align__(16) ull sw2[CH * 9 * 8]; // [i][k][pair]
    __shared__ uint8_t s2[CH * 392];              // t2 for this half (local)
    __shared__ int sh[8];

    for (int i = tid; i < CH * 900 / 4; i += 392)
        ((uint32_t*)st)[i] = 0x08080808u;
    if (tid < 8) sh[tid] = 0;
    __syncthreads();
    for (int idx = tid; idx < CH * HW; idx += 392) {
        int i = idx / HW, pp = idx - i * HW;
        int y = pp / WW, x = pp - y * WW;
        st[i * 900 + (y + 1) * 30 + (x + 1)] = g_t1[b * CH * HW + idx];
    }
    for (int idx = tid; idx < CH * 9 * 8; idx += 392) {
        int pr = idx & 7;
        int ik = idx >> 3;
        uint32_t lo = __float_as_uint(wc[(2 * pr) * (CH * 9) + ik]);
        uint32_t hi = __float_as_uint(wc[(2 * pr + 1) * (CH * 9) + ik]);
        sw2[idx] = ((ull)hi << 32) | lo;
    }
    __syncthreads();

    int y = p / WW, x = p - y * WW;
    const int q = (y + 1) * 30 + (x + 1);
    const ull ONE = 0x3f8000003f800000ull;
    ull h0 = 0, h1 = 0;

    for (int half = 0; half < 2; half++) {
        ull a[4][8];
#pragma unroll
        for (int pr = 0; pr < 4; pr++)
#pragma unroll
            for (int t = 0; t < 8; t++) a[pr][t] = 0ull;

#pragma unroll 1
        for (int i = 0; i < CH; i++) {
            const uint8_t* tp = st + i * 900 + q;
            const ull* wi = sw2 + i * 72 + half * 4;
#pragma unroll
            for (int r = 0; r < 3; r++) {
                int ro = (r - 1) * 30;
                int tv0 = tp[ro - 1], tv1 = tp[ro], tv2 = tp[ro + 1];
                if (min(min(tv0, tv1), tv2) < 8) {   // row-level warp-coherent skip
                    DO_TAP(tv0, wi + (r * 3 + 0) * 8, a);
                    DO_TAP(tv1, wi + (r * 3 + 1) * 8, a);
                    DO_TAP(tv2, wi + (r * 3 + 2) * 8, a);
                }
            }
        }
#pragma unroll
        for (int pr = 0; pr < 4; pr++) {
#pragma unroll
            for (int lane = 0; lane < 2; lane++) {
                int o = half * 8 + pr * 2 + lane;
                int t2 = 8;
#pragma unroll
                for (int t = TT - 1; t >= 0; t--) {
                    ull v = a[pr][t];
                    float f = __uint_as_float(lane ? (uint32_t)(v >> 32) : (uint32_t)v);
                    if (f >= 1.f) t2 = t;
                }
                s2[o * 392 + tid] = (uint8_t)t2;
                hist_add(h0, h1, t2);
            }
        }
    }
    hist_flush_warp(h0, h1, tid, sh);
    __syncthreads();
    // fused FirstSpikePool: min firing time over 2x2 windows of this half
    for (int idx = tid; idx < CH * 7 * PW; idx += 392) {
        int X = idx % PW;
        int r = idx / PW;
        int Yl = r % 7;
        int oc = r / 7;
        const uint8_t* base = s2 + oc * 392 + (Yl * 2) * WW + X * 2;
        int m = min(min((int)base[0], (int)base[1]), min((int)base[WW], (int)base[WW + 1]));
        g_tp[b * NPOOL + oc * PHW + (blockIdx.y * 7 + Yl) * PW + X] = (uint8_t)m;
    }
    if (tid < 8 && sh[tid]) atomicAdd(&g_cnt2[tid], sh[tid]);
}

// Kernel 45: FC1 crossing -> t3, then FC2 + readout IF, fused. 8 batches/block.
__global__ void __launch_bounds__(1024) k45(const float* __restrict__ w2,
                                            float* __restrict__ out) {
    int b0 = blockIdx.x * 8;
    int tid = threadIdx.x;
    int bl = tid >> 7, j = tid & 127;
    __shared__ uint8_t stp[8 * NPOOL];
    __shared__ float sw1[32 * NFC];
    __shared__ float sw2s[NOUT * NFC];
    __shared__ uint8_t s3[8 * NFC];
    __shared__ int sh3[8], sh4[8];
    {
        const uint4* src = (const uint4*)(g_tp + b0 * NPOOL);
        for (int i = tid; i < 8 * NPOOL / 16; i += 1024) ((uint4*)stp)[i] = src[i];
    }
    for (int i = tid; i < NOUT * NFC; i += 1024) sw2s[i] = w2[i];
    if (tid < 8) { sh3[tid] = 0; sh4[tid] = 0; }
    float C[8] = {0.f, 0.f, 0.f, 0.f, 0.f, 0.f, 0.f, 0.f};
    for (int c = 0; c < NPOOL / 32; c++) {
        __syncthreads();
        for (int idx = tid; idx < 32 * NFC; idx += 1024)
            sw1[idx] = g_w1T[c * 32 * NFC + idx];
        __syncthreads();
        if (j < NFC) {
            const uint8_t* tb = stp + bl * NPOOL + c * 32;
#pragma unroll 4
            for (int nl = 0; nl < 32; nl++) {
                int tv = tb[nl];                 // uniform across warp
                if (tv < 8) {
                    float w = sw1[nl * NFC + j];
                    switch (tv) {                 // intentional fall-through
                        case 0: C[0] += w; // fallthrough
                        case 1: C[1] += w; // fallthrough
                        case 2: C[2] += w; // fallthrough
                        case 3: C[3] += w; // fallthrough
                        case 4: C[4] += w; // fallthrough
                        case 5: C[5] += w; // fallthrough
                        case 6: C[6] += w; // fallthrough
                        case 7: C[7] += w;
                    }
                }
            }
        }
    }
    int t3 = 8;
    if (j < NFC) {
#pragma unroll
        for (int t = TT - 1; t >= 0; t--) if (C[t] >= 1.f) t3 = t;
        s3[bl * NFC + j] = (uint8_t)t3;
    }
    // cnt3 via ballot (all lanes participate)
#pragma unroll
    for (int t = 0; t < 8; t++) {
        unsigned bal = __ballot_sync(0xffffffffu, (j < NFC) && (t3 == t));
        if ((tid & 31) == 0 && bal) atomicAdd(&sh3[t], __popc(bal));
    }
    __syncthreads();
    if (j < NOUT) {
        int b = b0 + bl;
        float O[8] = {0.f, 0.f, 0.f, 0.f, 0.f, 0.f, 0.f, 0.f};
        const uint8_t* sb = s3 + bl * NFC;
        for (int jj = 0; jj < NFC; jj++) {
            int tv = sb[jj];                     // uniform across active lanes
            if (tv < 8) {
                float w = sw2s[j * NFC + jj];
                switch (tv) {
                    case 0: O[0] += w; break;
                    case 1: O[1] += w; break;
                    case 2: O[2] += w; break;
                    case 3: O[3] += w; break;
                    case 4: O[4] += w; break;
                    case 5: O[5] += w; break;
                    case 6: O[6] += w; break;
                    case 7: O[7] += w; break;
                }
            }
        }
        float v = 0.f; int first = 8;
#pragma unroll
        for (int t = 0; t < TT; t++) {
            v += O[t];
            if (v >= 1.f) {
                v = 0.f;
                if (first == 8) first = t;
                atomicAdd(&sh4[t], 1);
            }
        }
        out[b * NOUT + j] = (first < 8) ? (float)(TT - first) / (float)TT : 0.f;
    }
    __syncthreads();
    if (tid < 8) {
        if (sh3[tid]) atomicAdd(&g_cnt3[tid], sh3[tid]);
        if (sh4[tid]) atomicAdd(&g_cnt4[tid], sh4[tid]);
    }
}

__global__ void k6_final(float* __restrict__ out, int write_reg) {
    if (threadIdx.x == 0 && write_reg) {
        float m1 = 0.f, m2 = 0.f, m3 = 0.f, m4 = 0.f;
        for (int t = 0; t < TT; t++) {
            m1 = fmaxf(m1, (float)g_cnt1[t] / (float)N1);
            m2 = fmaxf(m2, (float)g_cnt2[t] / (float)N1);
            m3 = fmaxf(m3, (float)g_cnt3[t] / (float)(BB * NFC));
            m4 = fmaxf(m4, (float)g_cnt4[t] / (float)(BB * NOUT));
        }
        out[BB * NOUT] = m1 + m2 + m3 + m4;
    }
}

extern "C" void kernel_launch(void* const* d_in, const int* in_sizes, int n_in,
                              void* d_out, int out_size) {
    const float* x  = (const float*)d_in[0];
    const float* ws = (const float*)d_in[1];
    const float* wc = (const float*)d_in[2];
    const float* w1 = (const float*)d_in[3];
    const float* w2 = (const float*)d_in[4];
    float* out = (float*)d_out;

    k_zero<<<1, 32>>>();
    k_transpose_w1<<<(NFC * NPOOL + 255) / 256, 256>>>(w1);
    k1_sconv<<<BB, 256>>>(x, ws);
    {
        dim3 g(BB, 2);
        k2_conv<<<g, 392>>>(wc);
    }
    k45<<<BB / 8, 1024>>>(w2, out);
    k6_final<<<1, 1>>>(out, (out_size > BB * NOUT) ? 1 : 0);
}